// round 1
// baseline (speedup 1.0000x reference)
#include <cuda_runtime.h>
#include <math.h>

// Problem constants
constexpr int MT = 32768;   // B*C rows
constexpr int D  = 256;     // embedding dim
constexpr int BM = 128, BN = 128, BK = 16;

// Scratch (allocation-free: __device__ globals)
__device__ float g_bufA[MT * D];
__device__ float g_bufB[MT * D];
__device__ float g_sum[3 * D];
__device__ float g_sq[3 * D];
__device__ float g_a[3 * D];   // folded norm scale:  rstd*gamma
__device__ float g_c[3 * D];   // folded norm shift:  beta - mu*rstd*gamma

__device__ __forceinline__ float gelu_exact(float x) {
    return 0.5f * x * (1.0f + erff(x * 0.70710678118654752f));
}

__global__ void zero_stats_kernel() {
    int t = threadIdx.x;
    for (int i = t; i < 3 * D; i += blockDim.x) {
        g_sum[i] = 0.0f;
        g_sq[i]  = 0.0f;
    }
}

__global__ void finalize_stats_kernel(const float* __restrict__ gamma,
                                      const float* __restrict__ beta,
                                      int layer) {
    int n = threadIdx.x;  // 256 threads
    const float inv_m = 1.0f / (float)MT;
    float mu  = g_sum[layer * D + n] * inv_m;
    float var = g_sq[layer * D + n] * inv_m - mu * mu;
    float rstd = rsqrtf(var + 1e-5f);
    float a = rstd * gamma[n];
    g_a[layer * D + n] = a;
    g_c[layer * D + n] = beta[n] - mu * a;
}

// Y = gelu( norm(X) @ W + b ), optionally gathering X rows from an embedding
// table and optionally accumulating per-column sum / sumsq of Y.
template <bool GATHER, bool NORM, bool STATS>
__global__ __launch_bounds__(256)
void gemm_gelu_kernel(const float* __restrict__ A,      // MT x D  (or table if GATHER)
                      const int*   __restrict__ ids,    // MT gather ids (GATHER only)
                      const float* __restrict__ W,      // D x D row-major
                      const float* __restrict__ bias,   // D
                      int norm_layer,                   // index into g_a/g_c (NORM)
                      int stat_layer,                   // index into g_sum/g_sq (STATS)
                      float* __restrict__ out)          // MT x D
{
    __shared__ float As[BK][BM + 4];
    __shared__ float Bs[BK][BN];
    __shared__ float s_sum[BN];
    __shared__ float s_sq[BN];

    const int tid = threadIdx.x;
    const int tx  = tid & 15;   // N direction (16)
    const int ty  = tid >> 4;   // M direction (16)
    const int n0  = blockIdx.x * BN;
    const int m0  = blockIdx.y * BM;

    const float* na = NORM ? (g_a + norm_layer * D) : nullptr;
    const float* nc = NORM ? (g_c + norm_layer * D) : nullptr;

    float acc[8][8];
#pragma unroll
    for (int i = 0; i < 8; i++)
#pragma unroll
        for (int j = 0; j < 8; j++) acc[i][j] = 0.0f;

    for (int k0 = 0; k0 < D; k0 += BK) {
        // ---- load A tile (128 rows x 16 k), store transposed As[k][m] ----
#pragma unroll
        for (int l = 0; l < 2; l++) {
            int id4 = tid + l * 256;          // 512 float4s
            int row = id4 >> 2;               // 0..127
            int kq  = (id4 & 3) * 4;          // 0,4,8,12
            int gr  = m0 + row;
            const float* src;
            if (GATHER) {
                src = A + (size_t)ids[gr] * D + k0 + kq;
            } else {
                src = A + (size_t)gr * D + k0 + kq;
            }
            float4 v = *(const float4*)src;
            if (NORM) {
                float4 sa = *(const float4*)(na + k0 + kq);
                float4 sc = *(const float4*)(nc + k0 + kq);
                v.x = fmaf(v.x, sa.x, sc.x);
                v.y = fmaf(v.y, sa.y, sc.y);
                v.z = fmaf(v.z, sa.z, sc.z);
                v.w = fmaf(v.w, sa.w, sc.w);
            }
            As[kq + 0][row] = v.x;
            As[kq + 1][row] = v.y;
            As[kq + 2][row] = v.z;
            As[kq + 3][row] = v.w;
        }
        // ---- load B tile (16 k x 128 n), coalesced ----
#pragma unroll
        for (int l = 0; l < 2; l++) {
            int id4 = tid + l * 256;
            int r = id4 >> 5;                 // 0..15
            int c = (id4 & 31) * 4;           // 0..124
            float4 v = *(const float4*)(W + (size_t)(k0 + r) * D + n0 + c);
            *(float4*)&Bs[r][c] = v;
        }
        __syncthreads();

#pragma unroll
        for (int kk = 0; kk < BK; kk++) {
            float a[8], b[8];
#pragma unroll
            for (int i = 0; i < 8; i++) a[i] = As[kk][ty * 8 + i];
#pragma unroll
            for (int j = 0; j < 8; j++) b[j] = Bs[kk][tx * 8 + j];
#pragma unroll
            for (int i = 0; i < 8; i++)
#pragma unroll
                for (int j = 0; j < 8; j++)
                    acc[i][j] = fmaf(a[i], b[j], acc[i][j]);
        }
        __syncthreads();
    }

    // ---- epilogue: bias + exact GELU + store + (optional) column stats ----
    float bj[8];
#pragma unroll
    for (int j = 0; j < 8; j++) bj[j] = bias[n0 + tx * 8 + j];

    float csum[8], csq[8];
#pragma unroll
    for (int j = 0; j < 8; j++) { csum[j] = 0.0f; csq[j] = 0.0f; }

#pragma unroll
    for (int i = 0; i < 8; i++) {
        float vals[8];
#pragma unroll
        for (int j = 0; j < 8; j++) {
            float v = gelu_exact(acc[i][j] + bj[j]);
            vals[j] = v;
            if (STATS) { csum[j] += v; csq[j] += v * v; }
        }
        size_t off = (size_t)(m0 + ty * 8 + i) * D + n0 + tx * 8;
        *(float4*)(out + off)     = make_float4(vals[0], vals[1], vals[2], vals[3]);
        *(float4*)(out + off + 4) = make_float4(vals[4], vals[5], vals[6], vals[7]);
    }

    if (STATS) {
        if (tid < BN) { s_sum[tid] = 0.0f; s_sq[tid] = 0.0f; }
        __syncthreads();
#pragma unroll
        for (int j = 0; j < 8; j++) {
            atomicAdd(&s_sum[tx * 8 + j], csum[j]);
            atomicAdd(&s_sq[tx * 8 + j],  csq[j]);
        }
        __syncthreads();
        if (tid < BN) {
            atomicAdd(&g_sum[stat_layer * D + n0 + tid], s_sum[tid]);
            atomicAdd(&g_sq[stat_layer * D + n0 + tid],  s_sq[tid]);
        }
    }
}

extern "C" void kernel_launch(void* const* d_in, const int* in_sizes, int n_in,
                              void* d_out, int out_size) {
    // metadata order: perturbation_ids, table, W1,b1,W2,b2,W3,b3,W4,b4,
    //                 g1,be1,g2,be2,g3,be3
    const int*   ids   = (const int*)d_in[0];
    const float* table = (const float*)d_in[1];
    const float* W1 = (const float*)d_in[2];
    const float* b1 = (const float*)d_in[3];
    const float* W2 = (const float*)d_in[4];
    const float* b2 = (const float*)d_in[5];
    const float* W3 = (const float*)d_in[6];
    const float* b3 = (const float*)d_in[7];
    const float* W4 = (const float*)d_in[8];
    const float* b4 = (const float*)d_in[9];
    const float* g1  = (const float*)d_in[10];
    const float* be1 = (const float*)d_in[11];
    const float* g2  = (const float*)d_in[12];
    const float* be2 = (const float*)d_in[13];
    const float* g3  = (const float*)d_in[14];
    const float* be3 = (const float*)d_in[15];
    float* out = (float*)d_out;

    float *bufA, *bufB;
    cudaGetSymbolAddress((void**)&bufA, g_bufA);
    cudaGetSymbolAddress((void**)&bufB, g_bufB);

    dim3 grid(D / BN, MT / BM);   // (2, 256)
    dim3 block(256);

    zero_stats_kernel<<<1, 256>>>();

    // L1: gather + GEMM + gelu, accumulate stats[0]
    gemm_gelu_kernel<true, false, true><<<grid, block>>>(
        table, ids, W1, b1, /*norm*/0, /*stats*/0, bufA);
    finalize_stats_kernel<<<1, 256>>>(g1, be1, 0);

    // L2: norm(stats0) + GEMM + gelu, accumulate stats[1]
    gemm_gelu_kernel<false, true, true><<<grid, block>>>(
        bufA, nullptr, W2, b2, 0, 1, bufB);
    finalize_stats_kernel<<<1, 256>>>(g2, be2, 1);

    // L3: norm(stats1) + GEMM + gelu, accumulate stats[2]
    gemm_gelu_kernel<false, true, true><<<grid, block>>>(
        bufB, nullptr, W3, b3, 1, 2, bufA);
    finalize_stats_kernel<<<1, 256>>>(g3, be3, 2);

    // L4: norm(stats2) + GEMM + gelu -> output
    gemm_gelu_kernel<false, true, false><<<grid, block>>>(
        bufA, nullptr, W4, b4, 2, -1, out);
}

// round 3
// speedup vs baseline: 1.6208x; 1.6208x over previous
#include <cuda_runtime.h>
#include <math.h>
#include <stdint.h>

// Problem constants
constexpr int MT = 32768;   // B*C rows
constexpr int D  = 256;     // embedding dim

// Scratch (allocation-free: __device__ globals)
__device__ float g_bufA[MT * D];
__device__ float g_bufB[MT * D];
__device__ float g_sum[3 * D];
__device__ float g_sq[3 * D];
__device__ float g_a[3 * D];      // rstd*gamma
__device__ float g_c[3 * D];      // beta - mu*rstd*gamma
__device__ float g_W[4][D * D];   // folded, tf32-rounded weights
__device__ float g_bias[4][D];    // folded exact fp32 bias

__device__ __forceinline__ float gelu_exact(float x) {
    return 0.5f * x * (1.0f + erff(x * 0.70710678118654752f));
}

__device__ __forceinline__ uint32_t f2tf(float x) {
    uint32_t r;
    asm("cvt.rna.tf32.f32 %0, %1;" : "=r"(r) : "f"(x));
    return r;
}
__device__ __forceinline__ float tf32r(float x) {
    return __uint_as_float(f2tf(x));
}

__device__ __forceinline__ void cp16(void* smem_dst, const void* gsrc) {
    uint32_t s = (uint32_t)__cvta_generic_to_shared(smem_dst);
    asm volatile("cp.async.cg.shared.global [%0], [%1], 16;\n" :: "r"(s), "l"(gsrc));
}
#define CP_COMMIT asm volatile("cp.async.commit_group;\n" ::: "memory")
#define CP_WAIT0  asm volatile("cp.async.wait_group 0;\n" ::: "memory")

// ---------------- small prep kernels ----------------

__global__ void zero_stats_kernel() {
    int t = threadIdx.x;
    for (int i = t; i < 3 * D; i += blockDim.x) { g_sum[i] = 0.0f; g_sq[i] = 0.0f; }
}

// Layer 1 prep: W'=tf32(W1), bias'=b1
__global__ void prep_w1_kernel(const float* __restrict__ W1, const float* __restrict__ b1) {
    int k = blockIdx.x, n = threadIdx.x;
    g_W[0][k * D + n] = tf32r(W1[k * D + n]);
    if (k == 0) g_bias[0][n] = b1[n];
}

// finalize BN stats for `layer`, init next layer's bias with raw b
__global__ void finalize_stats_kernel(const float* __restrict__ gamma,
                                      const float* __restrict__ beta,
                                      const float* __restrict__ bias_next,
                                      int layer) {
    int n = threadIdx.x;
    const float inv_m = 1.0f / (float)MT;
    float mu  = g_sum[layer * D + n] * inv_m;
    float var = g_sq[layer * D + n] * inv_m - mu * mu;
    float rstd = rsqrtf(var + 1e-5f);
    float a = rstd * gamma[n];
    g_a[layer * D + n] = a;
    g_c[layer * D + n] = beta[n] - mu * a;
    g_bias[layer + 1][n] = bias_next[n];
}

// W'[k][n] = tf32( a[k] * W[k][n] )
__global__ void fold_w_kernel(const float* __restrict__ Wsrc, int dst_layer, int norm_layer) {
    int k = blockIdx.x, n = threadIdx.x;
    g_W[dst_layer][k * D + n] = tf32r(g_a[norm_layer * D + k] * Wsrc[k * D + n]);
}

// bias'[n] += sum_k c[k] * W[k][n]   (exact fp32)
__global__ void fold_bias_kernel(const float* __restrict__ Wsrc, int dst_layer, int norm_layer) {
    int n = threadIdx.x;
    int k0 = blockIdx.x * 32;
    float s = 0.0f;
#pragma unroll
    for (int k = 0; k < 32; k++)
        s += g_c[norm_layer * D + k0 + k] * Wsrc[(k0 + k) * D + n];
    atomicAdd(&g_bias[dst_layer][n], s);
}

// ---------------- main TF32 MMA layer kernel ----------------
// Y = gelu( X @ W' + bias' ), X optionally gathered from table via ids.
// CTA tile 128x128, K-block 32, 8 warps (4m x 2n), warp tile 32x64.

constexpr int ASTR = 36;                 // A smem row stride (floats)
constexpr int BSTR = 136;                // B smem row stride (floats)
constexpr int ASZ  = 128 * ASTR;         // 4608
constexpr int BSZ  = 32 * BSTR;          // 4352
constexpr int STG  = ASZ + BSZ;          // 8960 floats per stage
constexpr int SMEM_BYTES = 2 * STG * 4;  // 71680

template <bool GATHER, bool STATS>
__global__ __launch_bounds__(256, 2)
void mma_layer_kernel(const float* __restrict__ A,     // MT x D  (or table if GATHER)
                      const int*   __restrict__ ids,
                      int wlayer,                      // index into g_W / g_bias
                      int stat_layer,
                      float* __restrict__ out)
{
    extern __shared__ float smem[];
    const float* __restrict__ W    = g_W[wlayer];
    const float* __restrict__ bias = g_bias[wlayer];

    const int tid  = threadIdx.x;
    const int lane = tid & 31;
    const int warp = tid >> 5;
    const int wm   = warp >> 1;          // 0..3
    const int wn   = warp & 1;           // 0..1
    const int m0   = blockIdx.y * 128;
    const int n0   = blockIdx.x * 128;

    // --- A copy source pointers (gather resolved once) ---
    const int c4 = (tid & 7) * 4;
    const float* srcA[4];
#pragma unroll
    for (int t = 0; t < 4; t++) {
        int row = (tid >> 3) + t * 32;
        int gr  = m0 + row;
        int ar  = GATHER ? ids[gr] : gr;
        srcA[t] = A + (size_t)ar * D + c4;
    }

    auto load_stage = [&](int kb, int s) {
        float* As = smem + s * STG;
        float* Bs = As + ASZ;
        int k0 = kb * 32;
#pragma unroll
        for (int t = 0; t < 4; t++) {
            int row = (tid >> 3) + t * 32;
            cp16(As + row * ASTR + c4, srcA[t] + k0);
        }
#pragma unroll
        for (int t = 0; t < 4; t++) {
            int brow = (tid >> 5) + t * 8;
            cp16(Bs + brow * BSTR + lane * 4,
                 W + (size_t)(k0 + brow) * D + n0 + lane * 4);
        }
    };

    float acc[2][8][4];
#pragma unroll
    for (int mt = 0; mt < 2; mt++)
#pragma unroll
        for (int nt = 0; nt < 8; nt++)
#pragma unroll
            for (int q = 0; q < 4; q++) acc[mt][nt][q] = 0.0f;

    load_stage(0, 0); CP_COMMIT;

    const int r  = lane >> 2;   // 0..7
    const int ca = lane & 3;    // 0..3

#pragma unroll 1
    for (int kb = 0; kb < 8; kb++) {
        CP_WAIT0;
        __syncthreads();
        if (kb + 1 < 8) { load_stage(kb + 1, (kb + 1) & 1); CP_COMMIT; }

        const float* As = smem + (kb & 1) * STG + (wm * 32) * ASTR;
        const float* Bs = smem + (kb & 1) * STG + ASZ + wn * 64;

#pragma unroll
        for (int kk = 0; kk < 4; kk++) {
            uint32_t af[2][4];
#pragma unroll
            for (int mt = 0; mt < 2; mt++) {
                const float* p = As + (mt * 16 + r) * ASTR + kk * 8 + ca;
                float x0 = p[0], x1 = p[8 * ASTR], x2 = p[4], x3 = p[8 * ASTR + 4];
                if (GATHER) {
                    af[mt][0] = f2tf(x0); af[mt][1] = f2tf(x1);
                    af[mt][2] = f2tf(x2); af[mt][3] = f2tf(x3);
                } else {
                    af[mt][0] = __float_as_uint(x0); af[mt][1] = __float_as_uint(x1);
                    af[mt][2] = __float_as_uint(x2); af[mt][3] = __float_as_uint(x3);
                }
            }
            uint32_t bf[8][2];
#pragma unroll
            for (int nt = 0; nt < 8; nt++) {
                const float* q = Bs + (kk * 8 + ca) * BSTR + nt * 8 + r;
                bf[nt][0] = __float_as_uint(q[0]);
                bf[nt][1] = __float_as_uint(q[4 * BSTR]);
            }
#pragma unroll
            for (int mt = 0; mt < 2; mt++)
#pragma unroll
                for (int nt = 0; nt < 8; nt++) {
                    asm volatile(
                        "mma.sync.aligned.m16n8k8.row.col.f32.tf32.tf32.f32 "
                        "{%0,%1,%2,%3}, {%4,%5,%6,%7}, {%8,%9}, {%0,%1,%2,%3};\n"
                        : "+f"(acc[mt][nt][0]), "+f"(acc[mt][nt][1]),
                          "+f"(acc[mt][nt][2]), "+f"(acc[mt][nt][3])
                        : "r"(af[mt][0]), "r"(af[mt][1]), "r"(af[mt][2]), "r"(af[mt][3]),
                          "r"(bf[nt][0]), "r"(bf[nt][1]));
                }
        }
    }

    // ---------------- epilogue ----------------
    __syncthreads();   // done with smem tiles; reuse for stats
    float* s_sum = smem;
    float* s_sq  = smem + 128;
    if (STATS) {
        if (tid < 128) { s_sum[tid] = 0.0f; s_sq[tid] = 0.0f; }
        __syncthreads();
    }

    const int cc = (lane & 3) * 2;
    float csum[8][2], csq[8][2];
#pragma unroll
    for (int nt = 0; nt < 8; nt++) {
        csum[nt][0] = csum[nt][1] = 0.0f;
        csq[nt][0]  = csq[nt][1]  = 0.0f;
    }

#pragma unroll
    for (int nt = 0; nt < 8; nt++) {
        int col = n0 + wn * 64 + nt * 8 + cc;
        float b0 = bias[col], b1 = bias[col + 1];
#pragma unroll
        for (int mt = 0; mt < 2; mt++) {
            int row0 = m0 + wm * 32 + mt * 16 + r;
            float v00 = gelu_exact(acc[mt][nt][0] + b0);
            float v01 = gelu_exact(acc[mt][nt][1] + b1);
            float v10 = gelu_exact(acc[mt][nt][2] + b0);
            float v11 = gelu_exact(acc[mt][nt][3] + b1);
            if (STATS) {
                csum[nt][0] += v00 + v10;  csum[nt][1] += v01 + v11;
                csq[nt][0]  += v00 * v00 + v10 * v10;
                csq[nt][1]  += v01 * v01 + v11 * v11;
                // round stored activations to tf32 for the next layer's MMA
                v00 = tf32r(v00); v01 = tf32r(v01);
                v10 = tf32r(v10); v11 = tf32r(v11);
            }
            *(float2*)(out + (size_t)row0 * D + col)       = make_float2(v00, v01);
            *(float2*)(out + (size_t)(row0 + 8) * D + col) = make_float2(v10, v11);
        }
    }

    if (STATS) {
#pragma unroll
        for (int nt = 0; nt < 8; nt++) {
            int c = wn * 64 + nt * 8 + cc;
            atomicAdd(&s_sum[c],     csum[nt][0]);
            atomicAdd(&s_sum[c + 1], csum[nt][1]);
            atomicAdd(&s_sq[c],      csq[nt][0]);
            atomicAdd(&s_sq[c + 1],  csq[nt][1]);
        }
        __syncthreads();
        if (tid < 128) {
            atomicAdd(&g_sum[stat_layer * D + n0 + tid], s_sum[tid]);
            atomicAdd(&g_sq[stat_layer * D + n0 + tid],  s_sq[tid]);
        }
    }
}

// ---------------- launch ----------------

extern "C" void kernel_launch(void* const* d_in, const int* in_sizes, int n_in,
                              void* d_out, int out_size) {
    const int*   ids   = (const int*)d_in[0];
    const float* table = (const float*)d_in[1];
    const float* W1 = (const float*)d_in[2];
    const float* b1 = (const float*)d_in[3];
    const float* W2 = (const float*)d_in[4];
    const float* b2 = (const float*)d_in[5];
    const float* W3 = (const float*)d_in[6];
    const float* b3 = (const float*)d_in[7];
    const float* W4 = (const float*)d_in[8];
    const float* b4 = (const float*)d_in[9];
    const float* g1  = (const float*)d_in[10];
    const float* be1 = (const float*)d_in[11];
    const float* g2  = (const float*)d_in[12];
    const float* be2 = (const float*)d_in[13];
    const float* g3  = (const float*)d_in[14];
    const float* be3 = (const float*)d_in[15];
    float* out = (float*)d_out;

    float *bufA, *bufB;
    cudaGetSymbolAddress((void**)&bufA, g_bufA);
    cudaGetSymbolAddress((void**)&bufB, g_bufB);

    static bool attr_set = false;
    if (!attr_set) {
        cudaFuncSetAttribute(mma_layer_kernel<true,  true>,
                             cudaFuncAttributeMaxDynamicSharedMemorySize, SMEM_BYTES);
        cudaFuncSetAttribute(mma_layer_kernel<false, true>,
                             cudaFuncAttributeMaxDynamicSharedMemorySize, SMEM_BYTES);
        cudaFuncSetAttribute(mma_layer_kernel<false, false>,
                             cudaFuncAttributeMaxDynamicSharedMemorySize, SMEM_BYTES);
        attr_set = true;
    }

    dim3 grid(D / 128, MT / 128);   // (2, 256)
    dim3 block(256);

    zero_stats_kernel<<<1, 256>>>();
    prep_w1_kernel<<<D, D>>>(W1, b1);

    // L1: gather + tf32 GEMM + gelu, stats[0]
    mma_layer_kernel<true, true><<<grid, block, SMEM_BYTES>>>(table, ids, 0, 0, bufA);
    finalize_stats_kernel<<<1, D>>>(g1, be1, b2, 0);
    fold_w_kernel<<<D, D>>>(W2, 1, 0);
    fold_bias_kernel<<<8, D>>>(W2, 1, 0);

    // L2
    mma_layer_kernel<false, true><<<grid, block, SMEM_BYTES>>>(bufA, nullptr, 1, 1, bufB);
    finalize_stats_kernel<<<1, D>>>(g2, be2, b3, 1);
    fold_w_kernel<<<D, D>>>(W3, 2, 1);
    fold_bias_kernel<<<8, D>>>(W3, 2, 1);

    // L3
    mma_layer_kernel<false, true><<<grid, block, SMEM_BYTES>>>(bufB, nullptr, 2, 2, bufA);
    finalize_stats_kernel<<<1, D>>>(g3, be3, b4, 2);
    fold_w_kernel<<<D, D>>>(W4, 3, 2);
    fold_bias_kernel<<<8, D>>>(W4, 3, 2);

    // L4 -> out (exact fp32 store, no stats)
    mma_layer_kernel<false, false><<<grid, block, SMEM_BYTES>>>(bufA, nullptr, 3, -1, out);
}